// round 1
// baseline (speedup 1.0000x reference)
#include <cuda_runtime.h>
#include <math.h>

#define NN 20000
#define NE 320000
#define NG 256
#define DD 128
#define NL 4
#define AVG_LOG 2.8332133440562162f
#define EPSV 1e-5f
#define SLOPE 0.01f

// ---------------- scratch (static device memory; no allocation) ----------------
__device__ float g_h[NN * DD];
__device__ float g_P1[NN * DD];
__device__ float g_P2[NN * DD];
__device__ float g_agg[NN * 4 * DD];
__device__ float g_ph[NN * DD];
__device__ float g_phs[NN * DD];
__device__ float g_bond[4 * DD];
__device__ int   g_deg[NN];
__device__ int   g_off[NN + 1];
__device__ int   g_cur[NN];
__device__ int   g_esrc[NE];
__device__ int   g_eattr[NE];
__device__ float g_dinv[NN], g_amp[NN], g_att[NN];
__device__ float g_bnsum[DD], g_bnsq[DD];
__device__ float g_gsum[NG * DD];
__device__ float g_gcnt[NG];

// ---------------- setup kernels ----------------
__global__ void k_init_zero() {
    int i = blockIdx.x * blockDim.x + threadIdx.x;
    if (i < NN) { g_deg[i] = 0; g_cur[i] = 0; }
}

__global__ void k_count(const int* __restrict__ dst) {
    int e = blockIdx.x * blockDim.x + threadIdx.x;
    if (e < NE) atomicAdd(&g_deg[dst[e]], 1);
}

__global__ void k_scan() {
    __shared__ int s[1024];
    __shared__ int run;
    int t = threadIdx.x;
    if (t == 0) run = 0;
    for (int base = 0; base < NN; base += 1024) {
        __syncthreads();
        int r = run;
        int v = (base + t < NN) ? g_deg[base + t] : 0;
        s[t] = v;
        __syncthreads();
        for (int d2 = 1; d2 < 1024; d2 <<= 1) {
            int tv = (t >= d2) ? s[t - d2] : 0;
            __syncthreads();
            s[t] += tv;
            __syncthreads();
        }
        if (base + t < NN) g_off[base + t] = r + s[t] - v;
        if (t == 0) run = r + s[1023];
    }
    __syncthreads();
    if (t == 0) g_off[NN] = run;
}

__global__ void k_nodeprep() {
    int n = blockIdx.x * blockDim.x + threadIdx.x;
    if (n >= NN) return;
    float d = (float)g_deg[n];
    g_dinv[n] = 1.0f / fmaxf(d, 1.0f);
    float logd = log1pf(d);
    g_amp[n] = logd / AVG_LOG;
    g_att[n] = AVG_LOG / fmaxf(logd, EPSV);
}

__global__ void k_scatter(const int* __restrict__ src, const int* __restrict__ dst,
                          const int* __restrict__ attr) {
    int e = blockIdx.x * blockDim.x + threadIdx.x;
    if (e >= NE) return;
    int d = dst[e];
    int pos = g_off[d] + atomicAdd(&g_cur[d], 1);
    g_esrc[pos] = src[e];
    g_eattr[pos] = attr[e];
}

__global__ void k_embed(const int* __restrict__ x, const float* __restrict__ atom_emb) {
    int idx = blockIdx.x * blockDim.x + threadIdx.x;
    if (idx >= NN * DD) return;
    int n = idx >> 7, c = idx & 127;
    g_h[idx] = atom_emb[x[n] * DD + c];
}

// bondproj[b][c] = sum_k bond_emb[b][k] * pre_W[l][256+k][c] + pre_b[l][c]
__global__ void k_bond(const float* __restrict__ bond_emb, const float* __restrict__ preWl,
                       const float* __restrict__ preBl) {
    int t = threadIdx.x;            // 512 threads
    int b = t >> 7, c = t & 127;
    float a = preBl[c];
    for (int k = 0; k < DD; k++)
        a += bond_emb[b * DD + k] * preWl[(256 + k) * DD + c];
    g_bond[t] = a;
}

// ---------------- SGEMM: C[M,128] = epi(A'[M,K] @ B[K,128]) ----------------
// AMODE 0: A plain (lda given). AMODE 1: virtual post input (h|agg|amp*agg|att*agg).
// EPI 0: plain. EPI 1: +bias, leaky. EPI 2: +bias, leaky, *snorm[row].
template <int AMODE, int EPI>
__global__ void __launch_bounds__(256) gemm_k(const float* __restrict__ A, int lda,
                                              const float* __restrict__ B,
                                              const float* __restrict__ bias,
                                              float* __restrict__ C, int M, int K,
                                              const float* __restrict__ snorm) {
    __shared__ __align__(16) float As[16][64];
    __shared__ __align__(16) float Bs[16][128];
    int tid = threadIdx.x;
    int ty = tid >> 4, tx = tid & 15;
    int row0 = blockIdx.x * 64;
    int arow = tid >> 2, acol = (tid & 3) * 4;
    int brow = tid >> 4, bcol = (tid & 15) * 8;

    float acc[4][8];
#pragma unroll
    for (int i = 0; i < 4; i++)
#pragma unroll
        for (int j = 0; j < 8; j++) acc[i][j] = 0.f;

    for (int k0 = 0; k0 < K; k0 += 16) {
        // --- load A tile (64 x 16) ---
        float4 av = make_float4(0.f, 0.f, 0.f, 0.f);
        int r = row0 + arow;
        if (r < M) {
            if (AMODE == 0) {
                av = *(const float4*)&A[(size_t)r * lda + k0 + acol];
            } else {
                if (k0 < 128) {
                    av = *(const float4*)&g_h[r * DD + k0 + acol];
                } else {
                    int kk = k0 - 128;
                    float sc = 1.f;
                    if (kk >= 1024) { kk -= 1024; sc = g_att[r]; }
                    else if (kk >= 512) { kk -= 512; sc = g_amp[r]; }
                    av = *(const float4*)&g_agg[r * 512 + kk + acol];
                    av.x *= sc; av.y *= sc; av.z *= sc; av.w *= sc;
                }
            }
        }
        As[acol + 0][arow] = av.x;
        As[acol + 1][arow] = av.y;
        As[acol + 2][arow] = av.z;
        As[acol + 3][arow] = av.w;
        // --- load B tile (16 x 128) ---
        float4 b0 = *(const float4*)&B[(size_t)(k0 + brow) * DD + bcol];
        float4 b1 = *(const float4*)&B[(size_t)(k0 + brow) * DD + bcol + 4];
        *(float4*)&Bs[brow][bcol] = b0;
        *(float4*)&Bs[brow][bcol + 4] = b1;
        __syncthreads();
#pragma unroll
        for (int k = 0; k < 16; k++) {
            float4 a4 = *(float4*)&As[k][ty * 4];
            float4 bl = *(float4*)&Bs[k][tx * 8];
            float4 bh = *(float4*)&Bs[k][tx * 8 + 4];
            float aa[4] = {a4.x, a4.y, a4.z, a4.w};
            float bb[8] = {bl.x, bl.y, bl.z, bl.w, bh.x, bh.y, bh.z, bh.w};
#pragma unroll
            for (int i = 0; i < 4; i++)
#pragma unroll
                for (int j = 0; j < 8; j++) acc[i][j] += aa[i] * bb[j];
        }
        __syncthreads();
    }

#pragma unroll
    for (int i = 0; i < 4; i++) {
        int r = row0 + ty * 4 + i;
        if (r >= M) continue;
        float sn = (EPI == 2) ? snorm[r] : 1.f;
        float v[8];
#pragma unroll
        for (int j = 0; j < 8; j++) {
            float t = acc[i][j];
            if (EPI >= 1) {
                t += bias[tx * 8 + j];
                t = t > 0.f ? t : SLOPE * t;
            }
            if (EPI == 2) t *= sn;
            v[j] = t;
        }
        *(float4*)&C[r * DD + tx * 8] = make_float4(v[0], v[1], v[2], v[3]);
        *(float4*)&C[r * DD + tx * 8 + 4] = make_float4(v[4], v[5], v[6], v[7]);
    }
}

// ---------------- edge aggregation (CSR, node-parallel, atomic-free) ----------------
__global__ void k_edgeagg() {
    __shared__ __align__(16) float sb[4 * DD];
    int tid = threadIdx.x;
    for (int i = tid; i < 4 * DD; i += blockDim.x) sb[i] = g_bond[i];
    __syncthreads();
    int w = (blockIdx.x * blockDim.x + tid) >> 5;   // node id (grid sized exactly)
    int lane = tid & 31;
    int c0 = lane * 4;
    float4 base = *(float4*)&g_P1[w * DD + c0];
    int off = g_off[w], deg = g_deg[w];
    float s0 = 0, s1 = 0, s2 = 0, s3 = 0;
    float q0 = 0, q1 = 0, q2 = 0, q3 = 0;
    float x0 = -3.4e38f, x1 = -3.4e38f, x2 = -3.4e38f, x3 = -3.4e38f;
    float n0 = 3.4e38f, n1 = 3.4e38f, n2 = 3.4e38f, n3 = 3.4e38f;
    for (int i = 0; i < deg; i++) {
        int e = off + i;
        int src = g_esrc[e];
        int at = g_eattr[e];
        float4 p = *(float4*)&g_P2[src * DD + c0];
        float4 bb = *(float4*)&sb[at * DD + c0];
        float m0 = base.x + p.x + bb.x; m0 = m0 > 0 ? m0 : SLOPE * m0;
        float m1 = base.y + p.y + bb.y; m1 = m1 > 0 ? m1 : SLOPE * m1;
        float m2 = base.z + p.z + bb.z; m2 = m2 > 0 ? m2 : SLOPE * m2;
        float m3 = base.w + p.w + bb.w; m3 = m3 > 0 ? m3 : SLOPE * m3;
        s0 += m0; s1 += m1; s2 += m2; s3 += m3;
        q0 += m0 * m0; q1 += m1 * m1; q2 += m2 * m2; q3 += m3 * m3;
        x0 = fmaxf(x0, m0); x1 = fmaxf(x1, m1); x2 = fmaxf(x2, m2); x3 = fmaxf(x3, m3);
        n0 = fminf(n0, m0); n1 = fminf(n1, m1); n2 = fminf(n2, m2); n3 = fminf(n3, m3);
    }
    float dinv = g_dinv[w];
    bool nb = deg > 0;
    float me0 = s0 * dinv, me1 = s1 * dinv, me2 = s2 * dinv, me3 = s3 * dinv;
    float sd0 = nb ? sqrtf(fmaxf(q0 * dinv - me0 * me0, 0.f) + EPSV) : 0.f;
    float sd1 = nb ? sqrtf(fmaxf(q1 * dinv - me1 * me1, 0.f) + EPSV) : 0.f;
    float sd2 = nb ? sqrtf(fmaxf(q2 * dinv - me2 * me2, 0.f) + EPSV) : 0.f;
    float sd3 = nb ? sqrtf(fmaxf(q3 * dinv - me3 * me3, 0.f) + EPSV) : 0.f;
    if (!nb) { x0 = x1 = x2 = x3 = 0.f; n0 = n1 = n2 = n3 = 0.f; }
    float* a = &g_agg[w * 512];
    *(float4*)&a[c0]       = make_float4(me0, me1, me2, me3);
    *(float4*)&a[128 + c0] = make_float4(x0, x1, x2, x3);
    *(float4*)&a[256 + c0] = make_float4(n0, n1, n2, n3);
    *(float4*)&a[384 + c0] = make_float4(sd0, sd1, sd2, sd3);
}

// ---------------- batchnorm ----------------
__global__ void k_zero_bn() {
    int t = threadIdx.x;
    if (t < DD) { g_bnsum[t] = 0.f; g_bnsq[t] = 0.f; }
}

__global__ void k_bnstats() {
    __shared__ float ss[256], sq[256];
    int t = threadIdx.x;
    int c = t & 127, rg = t >> 7;
    float s = 0.f, q = 0.f;
    for (int rr = rg; rr < 128; rr += 2) {
        int r = blockIdx.x * 128 + rr;
        if (r < NN) {
            float v = g_phs[r * DD + c];
            s += v; q += v * v;
        }
    }
    ss[t] = s; sq[t] = q;
    __syncthreads();
    if (rg == 0) {
        atomicAdd(&g_bnsum[c], ss[c] + ss[c + 128]);
        atomicAdd(&g_bnsq[c], sq[c] + sq[c + 128]);
    }
}

__global__ void k_bnres(const float* __restrict__ gamma, const float* __restrict__ beta) {
    int idx = blockIdx.x * blockDim.x + threadIdx.x;
    if (idx >= NN * DD) return;
    int c = idx & 127;
    float mu = g_bnsum[c] * (1.0f / NN);
    float var = g_bnsq[c] * (1.0f / NN) - mu * mu;
    float v = gamma[c] * (g_phs[idx] - mu) * rsqrtf(var + EPSV) + beta[c];
    g_h[idx] += v;
}

// ---------------- pooling + readout ----------------
__global__ void k_zero_pool() {
    int i = blockIdx.x * blockDim.x + threadIdx.x;
    if (i < NG * DD) g_gsum[i] = 0.f;
    if (i < NG) g_gcnt[i] = 0.f;
}

__global__ void k_pool(const int* __restrict__ batch) {
    int idx = blockIdx.x * blockDim.x + threadIdx.x;
    if (idx >= NN * 32) return;
    int n = idx >> 5, q = idx & 31;
    int b = batch[n];
    float4 v = *(float4*)&g_h[n * DD + q * 4];
    atomicAdd(&g_gsum[b * DD + q * 4 + 0], v.x);
    atomicAdd(&g_gsum[b * DD + q * 4 + 1], v.y);
    atomicAdd(&g_gsum[b * DD + q * 4 + 2], v.z);
    atomicAdd(&g_gsum[b * DD + q * 4 + 3], v.w);
    if (q == 0) atomicAdd(&g_gcnt[b], 1.f);
}

__global__ void k_readout(const float* __restrict__ rW1, const float* __restrict__ rb1,
                          const float* __restrict__ rW2, const float* __restrict__ rb2,
                          const float* __restrict__ rW3, const float* __restrict__ rb3,
                          float* __restrict__ out) {
    __shared__ float sg[128], s1[64], s2[32];
    int b = blockIdx.x, t = threadIdx.x;   // 64 threads
    float cnt = fmaxf(g_gcnt[b], 1.f);
    for (int i = t; i < 128; i += 64) sg[i] = g_gsum[b * DD + i] / cnt;
    __syncthreads();
    float a = 0.f;
    for (int k = 0; k < 128; k++) a += sg[k] * rW1[k * 64 + t];
    s1[t] = fmaxf(a + rb1[t], 0.f);
    __syncthreads();
    if (t < 32) {
        float a2 = 0.f;
        for (int k = 0; k < 64; k++) a2 += s1[k] * rW2[k * 32 + t];
        s2[t] = fmaxf(a2 + rb2[t], 0.f);
    }
    __syncthreads();
    if (t < 32) {
        float p = s2[t] * rW3[t];
#pragma unroll
        for (int o = 16; o; o >>= 1) p += __shfl_down_sync(0xffffffffu, p, o);
        if (t == 0) out[b] = p + rb3[0];
    }
}

// ---------------- host launcher ----------------
static float* symf(const void* sym) {
    void* p = nullptr;
    cudaGetSymbolAddress(&p, sym);
    return (float*)p;
}

extern "C" void kernel_launch(void* const* d_in, const int* in_sizes, int n_in,
                              void* d_out, int out_size) {
    const int* x = (const int*)d_in[0];
    const int* batch = (const int*)d_in[1];
    const int* eidx = (const int*)d_in[2];    // [2,E]: src then dst
    const float* snorm = (const float*)d_in[3];
    const int* eattr = (const int*)d_in[4];
    const float* atom_emb = (const float*)d_in[5];
    const float* bond_emb = (const float*)d_in[6];
    const float* preW = (const float*)d_in[7];   // [4,384,128]
    const float* preB = (const float*)d_in[8];   // [4,128]
    const float* postW = (const float*)d_in[9];  // [4,1664,128]
    const float* postB = (const float*)d_in[10];
    const float* mixW = (const float*)d_in[11];  // [4,128,128]
    const float* mixB = (const float*)d_in[12];
    const float* gamma = (const float*)d_in[13];
    const float* beta = (const float*)d_in[14];
    const float* rW1 = (const float*)d_in[15];
    const float* rb1 = (const float*)d_in[16];
    const float* rW2 = (const float*)d_in[17];
    const float* rb2 = (const float*)d_in[18];
    const float* rW3 = (const float*)d_in[19];
    const float* rb3 = (const float*)d_in[20];
    float* out = (float*)d_out;

    float* p_h = symf(g_h);
    float* p_P1 = symf(g_P1);
    float* p_P2 = symf(g_P2);
    float* p_ph = symf(g_ph);
    float* p_phs = symf(g_phs);

    const int src_off = 0, dst_off = NE;
    const int GB = (NN + 63) / 64;   // 313 gemm blocks

    k_init_zero<<<(NN + 255) / 256, 256>>>();
    k_count<<<NE / 256, 256>>>(eidx + dst_off);
    k_scan<<<1, 1024>>>();
    k_nodeprep<<<(NN + 255) / 256, 256>>>();
    k_scatter<<<NE / 256, 256>>>(eidx + src_off, eidx + dst_off, eattr);
    k_embed<<<NN * DD / 256, 256>>>(x, atom_emb);

    for (int l = 0; l < NL; l++) {
        const float* preWl = preW + (size_t)l * 384 * DD;
        k_bond<<<1, 512>>>(bond_emb, preWl, preB + l * DD);
        gemm_k<0, 0><<<GB, 256>>>(p_h, DD, preWl, nullptr, p_P1, NN, DD, nullptr);
        gemm_k<0, 0><<<GB, 256>>>(p_h, DD, preWl + 128 * DD, nullptr, p_P2, NN, DD, nullptr);
        k_edgeagg<<<NN / 8, 256>>>();
        gemm_k<1, 1><<<GB, 256>>>(nullptr, 0, postW + (size_t)l * 1664 * DD,
                                  postB + l * DD, p_ph, NN, 1664, nullptr);
        k_zero_bn<<<1, 128>>>();
        gemm_k<0, 2><<<GB, 256>>>(p_ph, DD, mixW + (size_t)l * DD * DD,
                                  mixB + l * DD, p_phs, NN, DD, snorm);
        k_bnstats<<<(NN + 127) / 128, 256>>>();
        k_bnres<<<NN * DD / 256, 256>>>(gamma + l * DD, beta + l * DD);
    }

    k_zero_pool<<<(NG * DD + 255) / 256, 256>>>();
    k_pool<<<NN * 32 / 256, 256>>>(batch);
    k_readout<<<NG, 64>>>(rW1, rb1, rW2, rb2, rW3, rb3, out);
}

// round 4
// speedup vs baseline: 1.3541x; 1.3541x over previous
#include <cuda_runtime.h>
#include <cstdint>
#include <math.h>

#define NN 20000
#define NE 320000
#define NG 256
#define DD 128
#define NL 4
#define AVG_LOG 2.8332133440562162f
#define EPSV 1e-5f
#define SLOPE 0.01f

// ---------------- scratch (static device memory; no allocation) ----------------
__device__ float g_h[NN * DD];
__device__ float g_P1[NN * DD];
__device__ float g_P2[NN * DD];
__device__ float g_agg[NN * 4 * DD];
__device__ float g_ph[NN * DD];
__device__ float g_phs[NN * DD];
__device__ float g_bond[4 * DD];
__device__ int   g_deg[NN];
__device__ int   g_off[NN + 1];
__device__ int   g_cur[NN];
__device__ int   g_esrc[NE];
__device__ int   g_eattr[NE];
__device__ float g_dinv[NN], g_amp[NN], g_att[NN];
__device__ float g_bnsum[DD], g_bnsq[DD];
__device__ float g_gsum[NG * DD];
__device__ float g_gcnt[NG];

// ---------------- setup kernels ----------------
__global__ void k_init_zero() {
    int i = blockIdx.x * blockDim.x + threadIdx.x;
    if (i < NN) { g_deg[i] = 0; g_cur[i] = 0; }
}

__global__ void k_count(const int* __restrict__ dst) {
    int e = blockIdx.x * blockDim.x + threadIdx.x;
    if (e < NE) atomicAdd(&g_deg[dst[e]], 1);
}

__global__ void k_scan() {
    __shared__ int s[1024];
    __shared__ int run;
    int t = threadIdx.x;
    if (t == 0) run = 0;
    for (int base = 0; base < NN; base += 1024) {
        __syncthreads();
        int r = run;
        int v = (base + t < NN) ? g_deg[base + t] : 0;
        s[t] = v;
        __syncthreads();
        for (int d2 = 1; d2 < 1024; d2 <<= 1) {
            int tv = (t >= d2) ? s[t - d2] : 0;
            __syncthreads();
            s[t] += tv;
            __syncthreads();
        }
        if (base + t < NN) g_off[base + t] = r + s[t] - v;
        if (t == 0) run = r + s[1023];
    }
    __syncthreads();
    if (t == 0) g_off[NN] = run;
}

__global__ void k_nodeprep() {
    int n = blockIdx.x * blockDim.x + threadIdx.x;
    if (n >= NN) return;
    float d = (float)g_deg[n];
    g_dinv[n] = 1.0f / fmaxf(d, 1.0f);
    float logd = log1pf(d);
    g_amp[n] = logd / AVG_LOG;
    g_att[n] = AVG_LOG / fmaxf(logd, EPSV);
}

__global__ void k_scatter(const int* __restrict__ src, const int* __restrict__ dst,
                          const int* __restrict__ attr) {
    int e = blockIdx.x * blockDim.x + threadIdx.x;
    if (e >= NE) return;
    int d = dst[e];
    int pos = g_off[d] + atomicAdd(&g_cur[d], 1);
    g_esrc[pos] = src[e];
    g_eattr[pos] = attr[e];
}

__global__ void k_embed(const int* __restrict__ x, const float* __restrict__ atom_emb) {
    int idx = blockIdx.x * blockDim.x + threadIdx.x;
    if (idx >= NN * DD) return;
    int n = idx >> 7, c = idx & 127;
    g_h[idx] = atom_emb[x[n] * DD + c];
}

// bondproj[b][c] = sum_k bond_emb[b][k] * pre_W[l][256+k][c] + pre_b[l][c]
__global__ void k_bond(const float* __restrict__ bond_emb, const float* __restrict__ preWl,
                       const float* __restrict__ preBl) {
    int t = threadIdx.x;            // 512 threads
    int b = t >> 7, c = t & 127;
    float a = preBl[c];
    for (int k = 0; k < DD; k++)
        a += bond_emb[b * DD + k] * preWl[(256 + k) * DD + c];
    g_bond[t] = a;
}

// ---------------- 3xTF32 tensor-core GEMM (fp32-accurate) ----------------
// C[M,128] = epi(A'[M,K] @ B[K,128])
// AMODE 0: A plain fp32 row-major, lda=128. AMODE 1: virtual post input
//          (h | agg | amp*agg | att*agg), K=1664.
// EPI 0: plain. EPI 1: +bias, leaky. EPI 2: +bias, leaky, *snorm[row].
// Tiles: BM=128, BN=128, BK=32. 256 threads = 8 warps (2x4), warp tile 64x32.
// Each operand split a = ah + al (tf32 each); acc += Ah*Bh + Ah*Bl + Al*Bh.

__device__ __forceinline__ uint32_t f2tf(float f) {
    uint32_t u;
    asm("cvt.rna.tf32.f32 %0, %1;" : "=r"(u) : "f"(f));
    return u;
}

__device__ __forceinline__ void split_tf(float f, uint32_t& hi, uint32_t& lo) {
    hi = f2tf(f);
    lo = f2tf(f - __uint_as_float(hi));
}

__device__ __forceinline__ void mma_tf32(float c[4], const uint32_t a[4], const uint32_t b[2]) {
    asm volatile(
        "mma.sync.aligned.m16n8k8.row.col.f32.tf32.tf32.f32 "
        "{%0,%1,%2,%3}, {%4,%5,%6,%7}, {%8,%9}, {%0,%1,%2,%3};"
        : "+f"(c[0]), "+f"(c[1]), "+f"(c[2]), "+f"(c[3])
        : "r"(a[0]), "r"(a[1]), "r"(a[2]), "r"(a[3]), "r"(b[0]), "r"(b[1]));
}

#define APITCH 36
#define BPITCH 136

template <int AMODE, int EPI>
__global__ void __launch_bounds__(256) tgemm(const float* __restrict__ A,
                                             const float* __restrict__ B,
                                             const float* __restrict__ bias,
                                             float* __restrict__ C, int M, int K,
                                             const float* __restrict__ snorm) {
    __shared__ __align__(16) float sA[128 * APITCH];   // [m][k] m-major
    __shared__ __align__(16) float sB[32 * BPITCH];    // [k][n] k-major

    int tid = threadIdx.x;
    int lane = tid & 31, wid = tid >> 5;
    int wm = wid & 1, wn = wid >> 1;           // warp grid 2x4
    int g = lane >> 2, tg = lane & 3;
    int m0 = wm * 64, n0 = wn * 32;
    int row0 = blockIdx.x * 128;

    float acc[4][4][4];
#pragma unroll
    for (int i = 0; i < 4; i++)
#pragma unroll
        for (int j = 0; j < 4; j++)
#pragma unroll
            for (int q = 0; q < 4; q++) acc[i][j][q] = 0.f;

    for (int k0 = 0; k0 < K; k0 += 32) {
        // ---- load A tile: 128 rows x 32 k (m-major smem) ----
#pragma unroll
        for (int i = 0; i < 4; i++) {
            int idx = tid + i * 256;           // 0..1023
            int r = idx >> 3;                  // 0..127
            int kq = (idx & 7) * 4;            // 0,4,...,28
            float4 av = make_float4(0.f, 0.f, 0.f, 0.f);
            int gr = row0 + r;
            if (gr < M) {
                if (AMODE == 0) {
                    av = *(const float4*)&A[(size_t)gr * DD + k0 + kq];
                } else {
                    int kcol = k0 + kq;
                    if (kcol < 128) {
                        av = *(const float4*)&g_h[gr * DD + kcol];
                    } else {
                        int kk = kcol - 128;
                        float sc = 1.f;
                        if (kk >= 1024)      { kk -= 1024; sc = g_att[gr]; }
                        else if (kk >= 512)  { kk -= 512;  sc = g_amp[gr]; }
                        av = *(const float4*)&g_agg[gr * 512 + kk];
                        av.x *= sc; av.y *= sc; av.z *= sc; av.w *= sc;
                    }
                }
            }
            *(float4*)&sA[r * APITCH + kq] = av;
        }
        // ---- load B tile: 32 k x 128 n ----
#pragma unroll
        for (int i = 0; i < 4; i++) {
            int idx = tid + i * 256;           // 0..1023
            int kr = idx >> 5;                 // 0..31
            int nc = (idx & 31) * 4;
            float4 bv = *(const float4*)&B[(size_t)(k0 + kr) * DD + nc];
            *(float4*)&sB[kr * BPITCH + nc] = bv;
        }
        __syncthreads();

#pragma unroll
        for (int ks = 0; ks < 4; ks++) {
            int kk = ks * 8;
            // B fragments (hi/lo) for all 4 nf
            uint32_t bh[4][2], bl[4][2];
#pragma unroll
            for (int nf = 0; nf < 4; nf++) {
                int nc = n0 + nf * 8 + g;
                split_tf(sB[(kk + tg) * BPITCH + nc],     bh[nf][0], bl[nf][0]);
                split_tf(sB[(kk + tg + 4) * BPITCH + nc], bh[nf][1], bl[nf][1]);
            }
#pragma unroll
            for (int mf = 0; mf < 4; mf++) {
                int mr = m0 + mf * 16 + g;
                uint32_t ah[4], al[4];
                split_tf(sA[mr * APITCH + kk + tg],           ah[0], al[0]);
                split_tf(sA[(mr + 8) * APITCH + kk + tg],     ah[1], al[1]);
                split_tf(sA[mr * APITCH + kk + tg + 4],       ah[2], al[2]);
                split_tf(sA[(mr + 8) * APITCH + kk + tg + 4], ah[3], al[3]);
#pragma unroll
                for (int nf = 0; nf < 4; nf++) {
                    mma_tf32(acc[mf][nf], ah, bh[nf]);
                    mma_tf32(acc[mf][nf], ah, bl[nf]);
                    mma_tf32(acc[mf][nf], al, bh[nf]);
                }
            }
        }
        __syncthreads();
    }

    // ---- epilogue ----
#pragma unroll
    for (int mf = 0; mf < 4; mf++) {
        int r0 = row0 + m0 + mf * 16 + g;
        int r1 = r0 + 8;
        float sn0 = 1.f, sn1 = 1.f;
        if (EPI == 2) {
            if (r0 < M) sn0 = snorm[r0];
            if (r1 < M) sn1 = snorm[r1];
        }
#pragma unroll
        for (int nf = 0; nf < 4; nf++) {
            int col = n0 + nf * 8 + 2 * tg;
            float b0 = 0.f, b1 = 0.f;
            if (EPI >= 1) { b0 = bias[col]; b1 = bias[col + 1]; }
            float v0 = acc[mf][nf][0], v1 = acc[mf][nf][1];
            float v2 = acc[mf][nf][2], v3 = acc[mf][nf][3];
            if (EPI >= 1) {
                v0 += b0; v0 = v0 > 0.f ? v0 : SLOPE * v0;
                v1 += b1; v1 = v1 > 0.f ? v1 : SLOPE * v1;
                v2 += b0; v2 = v2 > 0.f ? v2 : SLOPE * v2;
                v3 += b1; v3 = v3 > 0.f ? v3 : SLOPE * v3;
            }
            if (EPI == 2) { v0 *= sn0; v1 *= sn0; v2 *= sn1; v3 *= sn1; }
            if (r0 < M) *(float2*)&C[(size_t)r0 * DD + col] = make_float2(v0, v1);
            if (r1 < M) *(float2*)&C[(size_t)r1 * DD + col] = make_float2(v2, v3);
        }
    }
}

// ---------------- edge aggregation (CSR, node-parallel, atomic-free) ----------------
__global__ void k_edgeagg() {
    __shared__ __align__(16) float sb[4 * DD];
    int tid = threadIdx.x;
    for (int i = tid; i < 4 * DD; i += blockDim.x) sb[i] = g_bond[i];
    __syncthreads();
    int w = (blockIdx.x * blockDim.x + tid) >> 5;   // node id (grid sized exactly)
    int lane = tid & 31;
    int c0 = lane * 4;
    float4 base = *(float4*)&g_P1[w * DD + c0];
    int off = g_off[w], deg = g_deg[w];
    float s0 = 0, s1 = 0, s2 = 0, s3 = 0;
    float q0 = 0, q1 = 0, q2 = 0, q3 = 0;
    float x0 = -3.4e38f, x1 = -3.4e38f, x2 = -3.4e38f, x3 = -3.4e38f;
    float n0 = 3.4e38f, n1 = 3.4e38f, n2 = 3.4e38f, n3 = 3.4e38f;
    for (int i = 0; i < deg; i++) {
        int e = off + i;
        int src = g_esrc[e];
        int at = g_eattr[e];
        float4 p = *(float4*)&g_P2[src * DD + c0];
        float4 bb = *(float4*)&sb[at * DD + c0];
        float m0 = base.x + p.x + bb.x; m0 = m0 > 0 ? m0 : SLOPE * m0;
        float m1 = base.y + p.y + bb.y; m1 = m1 > 0 ? m1 : SLOPE * m1;
        float m2 = base.z + p.z + bb.z; m2 = m2 > 0 ? m2 : SLOPE * m2;
        float m3 = base.w + p.w + bb.w; m3 = m3 > 0 ? m3 : SLOPE * m3;
        s0 += m0; s1 += m1; s2 += m2; s3 += m3;
        q0 += m0 * m0; q1 += m1 * m1; q2 += m2 * m2; q3 += m3 * m3;
        x0 = fmaxf(x0, m0); x1 = fmaxf(x1, m1); x2 = fmaxf(x2, m2); x3 = fmaxf(x3, m3);
        n0 = fminf(n0, m0); n1 = fminf(n1, m1); n2 = fminf(n2, m2); n3 = fminf(n3, m3);
    }
    float dinv = g_dinv[w];
    bool nb = deg > 0;
    float me0 = s0 * dinv, me1 = s1 * dinv, me2 = s2 * dinv, me3 = s3 * dinv;
    float sd0 = nb ? sqrtf(fmaxf(q0 * dinv - me0 * me0, 0.f) + EPSV) : 0.f;
    float sd1 = nb ? sqrtf(fmaxf(q1 * dinv - me1 * me1, 0.f) + EPSV) : 0.f;
    float sd2 = nb ? sqrtf(fmaxf(q2 * dinv - me2 * me2, 0.f) + EPSV) : 0.f;
    float sd3 = nb ? sqrtf(fmaxf(q3 * dinv - me3 * me3, 0.f) + EPSV) : 0.f;
    if (!nb) { x0 = x1 = x2 = x3 = 0.f; n0 = n1 = n2 = n3 = 0.f; }
    float* a = &g_agg[w * 512];
    *(float4*)&a[c0]       = make_float4(me0, me1, me2, me3);
    *(float4*)&a[128 + c0] = make_float4(x0, x1, x2, x3);
    *(float4*)&a[256 + c0] = make_float4(n0, n1, n2, n3);
    *(float4*)&a[384 + c0] = make_float4(sd0, sd1, sd2, sd3);
}

// ---------------- batchnorm ----------------
__global__ void k_zero_bn() {
    int t = threadIdx.x;
    if (t < DD) { g_bnsum[t] = 0.f; g_bnsq[t] = 0.f; }
}

__global__ void k_bnstats() {
    __shared__ float ss[256], sq[256];
    int t = threadIdx.x;
    int c = t & 127, rg = t >> 7;
    float s = 0.f, q = 0.f;
    for (int rr = rg; rr < 128; rr += 2) {
        int r = blockIdx.x * 128 + rr;
        if (r < NN) {
            float v = g_phs[r * DD + c];
            s += v; q += v * v;
        }
    }
    ss[t] = s; sq[t] = q;
    __syncthreads();
    if (rg == 0) {
        atomicAdd(&g_bnsum[c], ss[c] + ss[c + 128]);
        atomicAdd(&g_bnsq[c], sq[c] + sq[c + 128]);
    }
}

__global__ void k_bnres(const float* __restrict__ gamma, const float* __restrict__ beta) {
    int idx = blockIdx.x * blockDim.x + threadIdx.x;
    if (idx >= NN * DD) return;
    int c = idx & 127;
    float mu = g_bnsum[c] * (1.0f / NN);
    float var = g_bnsq[c] * (1.0f / NN) - mu * mu;
    float v = gamma[c] * (g_phs[idx] - mu) * rsqrtf(var + EPSV) + beta[c];
    g_h[idx] += v;
}

// ---------------- pooling + readout ----------------
__global__ void k_zero_pool() {
    int i = blockIdx.x * blockDim.x + threadIdx.x;
    if (i < NG * DD) g_gsum[i] = 0.f;
    if (i < NG) g_gcnt[i] = 0.f;
}

__global__ void k_pool(const int* __restrict__ batch) {
    int idx = blockIdx.x * blockDim.x + threadIdx.x;
    if (idx >= NN * 32) return;
    int n = idx >> 5, q = idx & 31;
    int b = batch[n];
    float4 v = *(float4*)&g_h[n * DD + q * 4];
    atomicAdd(&g_gsum[b * DD + q * 4 + 0], v.x);
    atomicAdd(&g_gsum[b * DD + q * 4 + 1], v.y);
    atomicAdd(&g_gsum[b * DD + q * 4 + 2], v.z);
    atomicAdd(&g_gsum[b * DD + q * 4 + 3], v.w);
    if (q == 0) atomicAdd(&g_gcnt[b], 1.f);
}

__global__ void k_readout(const float* __restrict__ rW1, const float* __restrict__ rb1,
                          const float* __restrict__ rW2, const float* __restrict__ rb2,
                          const float* __restrict__ rW3, const float* __restrict__ rb3,
                          float* __restrict__ out) {
    __shared__ float sg[128], s1[64], s2[32];
    int b = blockIdx.x, t = threadIdx.x;   // 64 threads
    float cnt = fmaxf(g_gcnt[b], 1.f);
    for (int i = t; i < 128; i += 64) sg[i] = g_gsum[b * DD + i] / cnt;
    __syncthreads();
    float a = 0.f;
    for (int k = 0; k < 128; k++) a += sg[k] * rW1[k * 64 + t];
    s1[t] = fmaxf(a + rb1[t], 0.f);
    __syncthreads();
    if (t < 32) {
        float a2 = 0.f;
        for (int k = 0; k < 64; k++) a2 += s1[k] * rW2[k * 32 + t];
        s2[t] = fmaxf(a2 + rb2[t], 0.f);
    }
    __syncthreads();
    if (t < 32) {
        float p = s2[t] * rW3[t];
#pragma unroll
        for (int o = 16; o; o >>= 1) p += __shfl_down_sync(0xffffffffu, p, o);
        if (t == 0) out[b] = p + rb3[0];
    }
}

// ---------------- host launcher ----------------
static float* symf(const void* sym) {
    void* p = nullptr;
    cudaGetSymbolAddress(&p, sym);
    return (float*)p;
}

extern "C" void kernel_launch(void* const* d_in, const int* in_sizes, int n_in,
                              void* d_out, int out_size) {
    const int* x = (const int*)d_in[0];
    const int* batch = (const int*)d_in[1];
    const int* eidx = (const int*)d_in[2];    // [2,E]: src then dst
    const float* snorm = (const float*)d_in[3];
    const int* eattr = (const int*)d_in[4];
    const float* atom_emb = (const float*)d_in[5];
    const float* bond_emb = (const float*)d_in[6];
    const float* preW = (const float*)d_in[7];   // [4,384,128]
    const float* preB = (const float*)d_in[8];   // [4,128]
    const float* postW = (const float*)d_in[9];  // [4,1664,128]
    const float* postB = (const float*)d_in[10];
    const float* mixW = (const float*)d_in[11];  // [4,128,128]
    const float* mixB = (const float*)d_in[12];
    const float* gamma = (const float*)d_in[13];
    const float* beta = (const float*)d_in[14];
    const float* rW1 = (const float*)d_in[15];
    const float* rb1 = (const float*)d_in[16];
    const float* rW2 = (const float*)d_in[17];
    const float* rb2 = (const float*)d_in[18];
    const float* rW3 = (const float*)d_in[19];
    const float* rb3 = (const float*)d_in[20];
    float* out = (float*)d_out;

    float* p_h = symf(g_h);
    float* p_P1 = symf(g_P1);
    float* p_P2 = symf(g_P2);
    float* p_ph = symf(g_ph);
    float* p_phs = symf(g_phs);

    const int src_off = 0, dst_off = NE;
    const int GB = (NN + 127) / 128;   // 157 gemm blocks

    k_init_zero<<<(NN + 255) / 256, 256>>>();
    k_count<<<NE / 256, 256>>>(eidx + dst_off);
    k_scan<<<1, 1024>>>();
    k_nodeprep<<<(NN + 255) / 256, 256>>>();
    k_scatter<<<NE / 256, 256>>>(eidx + src_off, eidx + dst_off, eattr);
    k_embed<<<NN * DD / 256, 256>>>(x, atom_emb);

    for (int l = 0; l < NL; l++) {
        const float* preWl = preW + (size_t)l * 384 * DD;
        k_bond<<<1, 512>>>(bond_emb, preWl, preB + l * DD);
        tgemm<0, 0><<<GB, 256>>>(p_h, preWl, nullptr, p_P1, NN, DD, nullptr);
        tgemm<0, 0><<<GB, 256>>>(p_h, preWl + 128 * DD, nullptr, p_P2, NN, DD, nullptr);
        k_edgeagg<<<NN / 8, 256>>>();
        tgemm<1, 1><<<GB, 256>>>(nullptr, postW + (size_t)l * 1664 * DD,
                                 postB + l * DD, p_ph, NN, 1664, nullptr);
        k_zero_bn<<<1, 128>>>();
        tgemm<0, 2><<<GB, 256>>>(p_ph, mixW + (size_t)l * DD * DD,
                                 mixB + l * DD, p_phs, NN, DD, snorm);
        k_bnstats<<<(NN + 127) / 128, 256>>>();
        k_bnres<<<NN * DD / 256, 256>>>(gamma + l * DD, beta + l * DD);
    }

    k_zero_pool<<<(NG * DD + 255) / 256, 256>>>();
    k_pool<<<NN * 32 / 256, 256>>>(batch);
    k_readout<<<NG, 64>>>(rW1, rb1, rW2, rb2, rW3, rb3, out);
}